// round 5
// baseline (speedup 1.0000x reference)
#include <cuda_runtime.h>
#include <cstdint>

// Problem constants
#define B_   4096
#define IN_  128
#define H_   1024
#define O_   64
#define T_   25
#define G4   (4*H_)        // 4096 gate columns
#define KC0  (O_ + H_)     // 1088  layer-0 dynamic K  [y | h1]
#define KC1  (2*H_)        // 2048  layer-1 K          [h1 | h2]

// ---------------------------------------------------------------------------
// Scratch (device globals; no allocation allowed)
// ---------------------------------------------------------------------------
__device__ float g_xs[B_*IN_];          // static input, tf32-rounded
__device__ float g_Ws[G4*IN_];          // W_ih0[:, :128], tf32
__device__ float g_W0[G4*KC0];          // [W_ih0[:,128:192] | W_hh0], tf32
__device__ float g_W1[G4*KC1];          // [W_ih1 | W_hh1], tf32
__device__ float g_Wo[O_*H_];           // W_out, tf32
__device__ float g_b0[G4];
__device__ float g_b1[G4];
__device__ float g_Gs[B_*G4];           // static gate pre-activations + b0
__device__ float g_G [B_*G4];           // per-step gates scratch
__device__ float g_x0[B_*KC0];          // [y_prev | h1]  (tf32-rounded)
__device__ float g_x1[B_*KC1];          // [h1 | h2]      (tf32-rounded)
__device__ float g_c1[B_*H_];
__device__ float g_c2[B_*H_];
__device__ float g_yt[B_*O_];

// ---------------------------------------------------------------------------
// Helpers
// ---------------------------------------------------------------------------
__device__ __forceinline__ float to_tf32(float x) {
    float r;
    asm("cvt.rna.tf32.f32 %0, %1;" : "=f"(r) : "f"(x));
    return r;
}
__device__ __forceinline__ float fast_exp2(float x) {
    float r; asm("ex2.approx.f32 %0, %1;" : "=f"(r) : "f"(x)); return r;
}
__device__ __forceinline__ float fast_rcp(float x) {
    float r; asm("rcp.approx.f32 %0, %1;" : "=f"(r) : "f"(x)); return r;
}
__device__ __forceinline__ float sigmoid_f(float x) {
    x = fminf(fmaxf(x, -30.f), 30.f);
    float e = fast_exp2(-x * 1.4426950408889634f);     // e^-x
    return fast_rcp(1.f + e);
}
__device__ __forceinline__ float tanh_f(float x) {
    x = fminf(fmaxf(x, -15.f), 15.f);
    float e = fast_exp2(2.f * x * 1.4426950408889634f); // e^{2x}
    return 1.f - 2.f * fast_rcp(e + 1.f);
}
__device__ __forceinline__ void cp16(void* s, const void* g) {
    uint32_t sa = (uint32_t)__cvta_generic_to_shared(s);
    asm volatile("cp.async.cg.shared.global [%0], [%1], 16;\n" :: "r"(sa), "l"(g));
}

// ---------------------------------------------------------------------------
// Prep kernels
// ---------------------------------------------------------------------------
// dst[r, 0:wa] = a[r*lda + k],  dst[r, wa:wa+wb] = b[r*ldb + k-wa], tf32-rounded
__global__ void pack_cat(const float* __restrict__ a, int lda, int wa,
                         const float* __restrict__ b, int ldb, int wb,
                         float* __restrict__ dst, int rows)
{
    int w = wa + wb;
    int n = rows * w;
    for (int i = blockIdx.x * blockDim.x + threadIdx.x; i < n;
         i += gridDim.x * blockDim.x) {
        int r = i / w, k = i - r * w;
        float v = (k < wa) ? a[r * lda + k] : b[r * ldb + (k - wa)];
        dst[i] = to_tf32(v);
    }
}

__global__ void add2(const float* __restrict__ a, const float* __restrict__ b,
                     float* __restrict__ d, int n)
{
    for (int i = blockIdx.x * blockDim.x + threadIdx.x; i < n;
         i += gridDim.x * blockDim.x)
        d[i] = a[i] + b[i];
}

__global__ void zerok(float* __restrict__ p, int n)
{
    for (int i = blockIdx.x * blockDim.x + threadIdx.x; i < n;
         i += gridDim.x * blockDim.x)
        p[i] = 0.f;
}

// ---------------------------------------------------------------------------
// TF32 GEMM:  C[M,N] = A[M,K] * W[N,K]^T (+ Cinit) (+ bias[n])
// BM=128, BN=64, BK=32; 8 warps (4 along M x 2 along N), warp tile 32x32.
// mma.sync.m16n8k8.tf32 ; single-buffer smem with cp.async.
// Requires: M%128==0, N%64==0, K%32==0, all row bases 16B-aligned.
// ---------------------------------------------------------------------------
#define BM 128
#define BN 64
#define BK 32

__global__ void __launch_bounds__(256)
gemm_tf32(int M, int N, int K,
          const float* __restrict__ A, int lda,
          const float* __restrict__ Bw, int ldb,
          float* __restrict__ C, int ldc,
          const float* __restrict__ Ci, int ldci,
          const float* __restrict__ bias)
{
    __shared__ float As[BM][BK + 4];
    __shared__ float Bs[BN][BK + 4];

    const int tid  = threadIdx.x;
    const int warp = tid >> 5;
    const int lane = tid & 31;
    const int wm = (warp & 3) * 32;   // warp M offset within block
    const int wn = (warp >> 2) * 32;  // warp N offset within block
    const int bm0 = blockIdx.y * BM;
    const int bn0 = blockIdx.x * BN;

    float c[2][4][4];
#pragma unroll
    for (int mt = 0; mt < 2; mt++)
#pragma unroll
        for (int nt = 0; nt < 4; nt++)
#pragma unroll
            for (int r = 0; r < 4; r++) c[mt][nt][r] = 0.f;

    const float* Ablk = A + bm0 * lda;
    const float* Bblk = Bw + bn0 * ldb;

    for (int k0 = 0; k0 < K; k0 += BK) {
        // ---- async loads into smem ----
#pragma unroll
        for (int i = 0; i < 4; i++) {                 // A: 1024 16B chunks
            int cc = tid + i * 256;
            int r = cc >> 3, kc = (cc & 7) << 2;
            cp16(&As[r][kc], Ablk + r * lda + k0 + kc);
        }
#pragma unroll
        for (int i = 0; i < 2; i++) {                 // B: 512 16B chunks
            int cc = tid + i * 256;
            int r = cc >> 3, kc = (cc & 7) << 2;
            cp16(&Bs[r][kc], Bblk + r * ldb + k0 + kc);
        }
        asm volatile("cp.async.commit_group;\n" ::);
        asm volatile("cp.async.wait_group 0;\n" ::);
        __syncthreads();

        // ---- compute: 4 k-steps of 8 ----
#pragma unroll
        for (int kk = 0; kk < 4; kk++) {
            const int kb = kk * 8 + (lane & 3);
            uint32_t af[2][4], bf[4][2];
#pragma unroll
            for (int mt = 0; mt < 2; mt++) {
                int m = wm + mt * 16 + (lane >> 2);
                af[mt][0] = __float_as_uint(As[m    ][kb    ]);
                af[mt][1] = __float_as_uint(As[m + 8][kb    ]);
                af[mt][2] = __float_as_uint(As[m    ][kb + 4]);
                af[mt][3] = __float_as_uint(As[m + 8][kb + 4]);
            }
#pragma unroll
            for (int nt = 0; nt < 4; nt++) {
                int n = wn + nt * 8 + (lane >> 2);
                bf[nt][0] = __float_as_uint(Bs[n][kb    ]);
                bf[nt][1] = __float_as_uint(Bs[n][kb + 4]);
            }
#pragma unroll
            for (int mt = 0; mt < 2; mt++)
#pragma unroll
                for (int nt = 0; nt < 4; nt++)
                    asm volatile(
                        "mma.sync.aligned.m16n8k8.row.col.f32.tf32.tf32.f32 "
                        "{%0,%1,%2,%3}, {%4,%5,%6,%7}, {%8,%9}, {%0,%1,%2,%3};\n"
                        : "+f"(c[mt][nt][0]), "+f"(c[mt][nt][1]),
                          "+f"(c[mt][nt][2]), "+f"(c[mt][nt][3])
                        : "r"(af[mt][0]), "r"(af[mt][1]),
                          "r"(af[mt][2]), "r"(af[mt][3]),
                          "r"(bf[nt][0]), "r"(bf[nt][1]));
        }
        __syncthreads();
    }

    // ---- epilogue ----
#pragma unroll
    for (int mt = 0; mt < 2; mt++) {
#pragma unroll
        for (int nt = 0; nt < 4; nt++) {
            int m = bm0 + wm + mt * 16 + (lane >> 2);
            int n = bn0 + wn + nt * 8 + ((lane & 3) << 1);
            float bv0 = bias ? bias[n]     : 0.f;
            float bv1 = bias ? bias[n + 1] : 0.f;
            float v0 = c[mt][nt][0] + bv0;
            float v1 = c[mt][nt][1] + bv1;
            float v2 = c[mt][nt][2] + bv0;
            float v3 = c[mt][nt][3] + bv1;
            if (Ci) {
                v0 += Ci[m * ldci + n];
                v1 += Ci[m * ldci + n + 1];
                v2 += Ci[(m + 8) * ldci + n];
                v3 += Ci[(m + 8) * ldci + n + 1];
            }
            C[m * ldc + n]           = v0;
            C[m * ldc + n + 1]       = v1;
            C[(m + 8) * ldc + n]     = v2;
            C[(m + 8) * ldc + n + 1] = v3;
        }
    }
}

// ---------------------------------------------------------------------------
// LSTM cell (elementwise). Gate layout in G: [i | f | g | o] blocks of H_.
// Writes new c (fp32) and new h (tf32-rounded) to one or two destinations.
// Launch: 4096 blocks x 256 threads (one thread per (batch, 4 hidden units)).
// ---------------------------------------------------------------------------
__global__ void lstm_cell(const float* __restrict__ G, float* __restrict__ cst,
                          float* __restrict__ h1, int ld1,
                          float* __restrict__ h2, int ld2)
{
    int idx = blockIdx.x * blockDim.x + threadIdx.x;
    int b = idx >> 8;
    int h = (idx & 255) << 2;

    const float4 vi = *(const float4*)(G + b * G4 + h);
    const float4 vf = *(const float4*)(G + b * G4 + H_ + h);
    const float4 vg = *(const float4*)(G + b * G4 + 2 * H_ + h);
    const float4 vo = *(const float4*)(G + b * G4 + 3 * H_ + h);
    float4 vc = *(float4*)(cst + b * H_ + h);

    float4 nc, nh;
#define CELLC(X) {                                                        \
        float ii = sigmoid_f(vi.X), ff = sigmoid_f(vf.X);                 \
        float gg = tanh_f(vg.X),    oo = sigmoid_f(vo.X);                 \
        nc.X = ff * vc.X + ii * gg;                                       \
        nh.X = to_tf32(oo * tanh_f(nc.X)); }
    CELLC(x) CELLC(y) CELLC(z) CELLC(w)
#undef CELLC

    *(float4*)(cst + b * H_ + h) = nc;
    *(float4*)(h1 + b * ld1 + h) = nh;
    if (h2) *(float4*)(h2 + b * ld2 + h) = nh;
}

// ---------------------------------------------------------------------------
// Scatter step output into d_out[:, t, :] and feedback columns x0[:, 0:64].
// Launch: 256 blocks x 256 threads (65536 = 4096 * 16 float4 chunks).
// ---------------------------------------------------------------------------
__global__ void scatter_y(const float* __restrict__ y, float* __restrict__ out,
                          float* __restrict__ x0, int t)
{
    int idx = blockIdx.x * blockDim.x + threadIdx.x;
    int b = idx >> 4;
    int j = (idx & 15) << 2;
    float4 v = *(const float4*)(y + b * O_ + j);
    *(float4*)(out + b * (T_ * O_) + t * O_ + j) = v;
    float4 r;
    r.x = to_tf32(v.x); r.y = to_tf32(v.y);
    r.z = to_tf32(v.z); r.w = to_tf32(v.w);
    *(float4*)(x0 + b * KC0 + j) = r;
}

// ---------------------------------------------------------------------------
// Launch
// ---------------------------------------------------------------------------
extern "C" void kernel_launch(void* const* d_in, const int* in_sizes, int n_in,
                              void* d_out, int out_size)
{
    (void)in_sizes; (void)n_in; (void)out_size;
    const float* sIn  = (const float*)d_in[0];
    const float* Wih0 = (const float*)d_in[1];
    const float* Whh0 = (const float*)d_in[2];
    const float* bih0 = (const float*)d_in[3];
    const float* bhh0 = (const float*)d_in[4];
    const float* Wih1 = (const float*)d_in[5];
    const float* Whh1 = (const float*)d_in[6];
    const float* bih1 = (const float*)d_in[7];
    const float* bhh1 = (const float*)d_in[8];
    const float* Wout = (const float*)d_in[9];
    const float* bout = (const float*)d_in[10];
    float* out = (float*)d_out;

    float *xs, *Ws, *W0, *W1, *Wo, *b0, *b1, *Gs, *G, *x0, *x1, *c1, *c2, *yt;
    cudaGetSymbolAddress((void**)&xs, g_xs);
    cudaGetSymbolAddress((void**)&Ws, g_Ws);
    cudaGetSymbolAddress((void**)&W0, g_W0);
    cudaGetSymbolAddress((void**)&W1, g_W1);
    cudaGetSymbolAddress((void**)&Wo, g_Wo);
    cudaGetSymbolAddress((void**)&b0, g_b0);
    cudaGetSymbolAddress((void**)&b1, g_b1);
    cudaGetSymbolAddress((void**)&Gs, g_Gs);
    cudaGetSymbolAddress((void**)&G,  g_G);
    cudaGetSymbolAddress((void**)&x0, g_x0);
    cudaGetSymbolAddress((void**)&x1, g_x1);
    cudaGetSymbolAddress((void**)&c1, g_c1);
    cudaGetSymbolAddress((void**)&c2, g_c2);
    cudaGetSymbolAddress((void**)&yt, g_yt);

    const int TPB = 256;

    // ---- pack (tf32-round) weights / static, fold biases ----
    pack_cat<<<512, TPB>>>(sIn, IN_, IN_, nullptr, 0, 0, xs, B_);
    pack_cat<<<2048, TPB>>>(Wih0, IN_ + O_, IN_, nullptr, 0, 0, Ws, G4);
    pack_cat<<<2048, TPB>>>(Wih0 + IN_, IN_ + O_, O_, Whh0, H_, H_, W0, G4);
    pack_cat<<<4096, TPB>>>(Wih1, H_, H_, Whh1, H_, H_, W1, G4);
    pack_cat<<<64, TPB>>>(Wout, H_, H_, nullptr, 0, 0, Wo, O_);
    add2<<<16, TPB>>>(bih0, bhh0, b0, G4);
    add2<<<16, TPB>>>(bih1, bhh1, b1, G4);

    // ---- zero recurrent state (must reset every replay) ----
    zerok<<<2048, TPB>>>(x0, B_ * KC0);
    zerok<<<4096, TPB>>>(x1, B_ * KC1);
    zerok<<<2048, TPB>>>(c1, B_ * H_);
    zerok<<<2048, TPB>>>(c2, B_ * H_);

    // ---- one-time static gate contribution: Gs = static @ Ws^T + b0 ----
    dim3 gridMain(G4 / BN, B_ / BM);  // (64, 32)
    gemm_tf32<<<gridMain, 256>>>(B_, G4, IN_, xs, IN_, Ws, IN_,
                                 Gs, G4, nullptr, 0, b0);

    dim3 gridOut(O_ / BN, B_ / BM);   // (1, 32)
    for (int t = 0; t < T_; t++) {
        // layer 0: G = [y|h1] @ [Wy|Whh0]^T + Gs
        gemm_tf32<<<gridMain, 256>>>(B_, G4, KC0, x0, KC0, W0, KC0,
                                     G, G4, Gs, G4, nullptr);
        lstm_cell<<<4096, 256>>>(G, c1, x0 + O_, KC0, x1, KC1);

        // layer 1: G = [h1|h2] @ [Wih1|Whh1]^T + b1
        gemm_tf32<<<gridMain, 256>>>(B_, G4, KC1, x1, KC1, W1, KC1,
                                     G, G4, nullptr, 0, b1);
        lstm_cell<<<4096, 256>>>(G, c2, x1 + H_, KC1, nullptr, 0);

        // output: y = h2 @ Wout^T + bout
        gemm_tf32<<<gridOut, 256>>>(B_, O_, H_, x1 + H_, KC1, Wo, H_,
                                    yt, O_, nullptr, 0, bout);
        scatter_y<<<256, 256>>>(yt, out, x0, t);
    }
}